// round 15
// baseline (speedup 1.0000x reference)
#include <cuda_runtime.h>
#include <cuda_fp16.h>
#include <math.h>
#include <stdint.h>

// ---------------- problem constants ----------------
#define LSEQ 2048
#define BB   8
#define DD   1024
#define ZZ   128
#define HH   2048
#define NN   16
#define MROWS (LSEQ*BB)           // 16384
#define NBASE (ZZ+HH+2*DD)        // 4224
#define EMA_C  128
#define EMA_NC (LSEQ/EMA_C)       // 16
#define BD (BB*DD)                // 8192

typedef __half h16;

// ---------------- scratch ----------------
__device__ h16 g_uh [(size_t)MROWS*DD];
__device__ h16 g_hxh[(size_t)MROWS*DD];
__device__ h16 g_vh [(size_t)MROWS*HH];
__device__ h16 g_rh [(size_t)MROWS*HH];
__device__ h16 g_xnh[(size_t)MROWS*DD];
__device__ h16 g_mxh[(size_t)MROWS*DD];
__device__ h16 g_qh [(size_t)BB*LSEQ*ZZ];
__device__ h16 g_ath[(size_t)BB*LSEQ*LSEQ];
__device__ h16 g_hrh[(size_t)MROWS*HH];
__device__ h16 g_vw [(size_t)HH*DD];
__device__ h16 g_mxw[(size_t)NBASE*DD];
__device__ h16 g_hw [(size_t)DD*HH];
__device__ h16 g_k  [(size_t)BB*LSEQ*ZZ];
__device__ h16 g_vT [(size_t)BB*HH*LSEQ];
__device__ float g_sEnd [(size_t)EMA_NC*BD*NN];   // 8 MB
__device__ float g_sInit[(size_t)EMA_NC*BD*NN];   // 8 MB

// ---------------- math helpers ----------------
__device__ __forceinline__ float sigm_(float x){ return 1.f/(1.f+expf(-x)); }
__device__ __forceinline__ float silu_(float x){ return x/(1.f+expf(-x)); }
__device__ __forceinline__ float laplace_(float x){
    const float inv = (float)(1.0/(0.282095*1.4142135623730951));
    return 0.5f*(1.f + erff((x - 0.707107f) * inv));
}
__device__ __forceinline__ uint32_t sm_u32(const void* p){
    uint32_t a;
    asm("{ .reg .u64 t; cvta.to.shared.u64 t, %1; cvt.u32.u64 %0, t; }" : "=r"(a) : "l"(p));
    return a;
}
__device__ __forceinline__ void ldm4(uint32_t* r, uint32_t addr){
    asm volatile("ldmatrix.sync.aligned.m8n8.x4.shared.b16 {%0,%1,%2,%3}, [%4];"
        : "=r"(r[0]),"=r"(r[1]),"=r"(r[2]),"=r"(r[3]) : "r"(addr));
}
__device__ __forceinline__ void mma16816(float* c, const uint32_t* a, uint32_t b0, uint32_t b1){
    asm volatile("mma.sync.aligned.m16n8k16.row.col.f32.f16.f16.f32 "
        "{%0,%1,%2,%3}, {%4,%5,%6,%7}, {%8,%9}, {%0,%1,%2,%3};"
        : "+f"(c[0]),"+f"(c[1]),"+f"(c[2]),"+f"(c[3])
        : "r"(a[0]),"r"(a[1]),"r"(a[2]),"r"(a[3]),"r"(b0),"r"(b1));
}
#define CPA(dst, src) asm volatile("cp.async.cg.shared.global [%0], [%1], 16;" :: "r"(dst), "l"(src))

__device__ __forceinline__ void st2(h16* H, size_t idx, float v0, float v1){
    __half2 t; t.x=__float2half(v0); t.y=__float2half(v1);
    *(__half2*)(H+idx) = t;
}
__device__ __forceinline__ uint2 pack4(float4 v){
    uint2 h;
    h16 h0=__float2half(v.x), h1=__float2half(v.y), h2=__float2half(v.z), h3=__float2half(v.w);
    h.x = (uint32_t)__half_as_ushort(h0) | ((uint32_t)__half_as_ushort(h1)<<16);
    h.y = (uint32_t)__half_as_ushort(h2) | ((uint32_t)__half_as_ushort(h3)<<16);
    return h;
}

// ---------------- LayerNorm: fp16 out only ----------------
__global__ __launch_bounds__(256) void ln_kernel(
    const float* __restrict__ x, const float* __restrict__ w,
    const float* __restrict__ b, h16* __restrict__ oh)
{
    long row = blockIdx.x;
    int tid = threadIdx.x;
    float4 v = ((const float4*)(x + row*DD))[tid];
    float s  = v.x+v.y+v.z+v.w;
    float ss = fmaf(v.x,v.x, fmaf(v.y,v.y, fmaf(v.z,v.z, v.w*v.w)));
    #pragma unroll
    for (int o=16;o>0;o>>=1){
        s  += __shfl_xor_sync(0xffffffffu, s, o);
        ss += __shfl_xor_sync(0xffffffffu, ss, o);
    }
    __shared__ float sh0[8], sh1[8];
    int wid = tid>>5, lane = tid&31;
    if (lane==0){ sh0[wid]=s; sh1[wid]=ss; }
    __syncthreads();
    float S=0.f, SS=0.f;
    #pragma unroll
    for (int i=0;i<8;i++){ S += sh0[i]; SS += sh1[i]; }
    float mu  = S*(1.f/DD);
    float var = SS*(1.f/DD) - mu*mu;
    float inv = rsqrtf(var + 1e-5f);
    float4 wv = ((const float4*)w)[tid];
    float4 bv = ((const float4*)b)[tid];
    float4 o;
    o.x = (v.x-mu)*inv*wv.x + bv.x;
    o.y = (v.y-mu)*inv*wv.y + bv.y;
    o.z = (v.z-mu)*inv*wv.z + bv.z;
    o.w = (v.w-mu)*inv*wv.w + bv.w;
    *(uint2*)(oh + row*DD + tid*4) = pack4(o);
}

// ---------------- EMA parallel scan ----------------
__global__ __launch_bounds__(256) void ema1_kernel(
    const h16* __restrict__ xn,
    const float* __restrict__ delta, const float* __restrict__ alpha,
    const float* __restrict__ beta_e, float* __restrict__ sEnd)
{
    int t = blockIdx.x*256 + threadIdx.x;
    int gid = t & (BD-1);
    int c   = t >> 13;
    int d   = gid & (DD-1);
    float q[NN], pb[NN], s[NN];
    #pragma unroll
    for (int n=0;n<NN;n++){
        float p = sigm_(delta[d*NN+n]);
        q[n]  = 1.f - p*sigm_(alpha[d*NN+n]);
        pb[n] = p*beta_e[d*NN+n];
        s[n]  = 0.f;
    }
    const h16* xp = xn + (size_t)c*EMA_C*BD + gid;
    for (int l=0; l<EMA_C; l++){
        float xc = __half2float(xp[(size_t)l*BD]);
        #pragma unroll
        for (int n=0;n<NN;n++)
            s[n] = fmaf(q[n], s[n], pb[n]*xc);
    }
    float* o = sEnd + (size_t)t*NN;
    #pragma unroll
    for (int n=0;n<NN;n+=4)
        *(float4*)(o+n) = make_float4(s[n],s[n+1],s[n+2],s[n+3]);
}

__global__ __launch_bounds__(256) void ema2_kernel(
    const float* __restrict__ delta, const float* __restrict__ alpha,
    const float* __restrict__ sEnd, float* __restrict__ sInit)
{
    int gid = blockIdx.x*256 + threadIdx.x;   // 0..8191
    int d   = gid & (DD-1);
    float qc[NN], S[NN];
    #pragma unroll
    for (int n=0;n<NN;n++){
        float p = sigm_(delta[d*NN+n]);
        float q = 1.f - p*sigm_(alpha[d*NN+n]);
        float tq = q;
        #pragma unroll
        for (int i=0;i<7;i++) tq = tq*tq;     // q^128
        qc[n] = tq;
        S[n]  = 0.f;
    }
    for (int c=0; c<EMA_NC; c++){
        size_t idx = ((size_t)c*BD + gid)*NN;
        float* oi = sInit + idx;
        const float* ei = sEnd + idx;
        #pragma unroll
        for (int n=0;n<NN;n+=4){
            *(float4*)(oi+n) = make_float4(S[n],S[n+1],S[n+2],S[n+3]);
            float4 e = *(const float4*)(ei+n);
            S[n]   = fmaf(qc[n],   S[n],   e.x);
            S[n+1] = fmaf(qc[n+1], S[n+1], e.y);
            S[n+2] = fmaf(qc[n+2], S[n+2], e.z);
            S[n+3] = fmaf(qc[n+3], S[n+3], e.w);
        }
    }
}

__global__ __launch_bounds__(256) void ema3_kernel(
    const h16* __restrict__ xn,
    const float* __restrict__ delta, const float* __restrict__ alpha,
    const float* __restrict__ beta_e, const float* __restrict__ gamma_e,
    const float* __restrict__ omega, const float* __restrict__ sInit,
    h16* __restrict__ mh)
{
    int t = blockIdx.x*256 + threadIdx.x;
    int gid = t & (BD-1);
    int c   = t >> 13;
    int d   = gid & (DD-1);
    float q[NN], pb[NN], g[NN], s[NN];
    #pragma unroll
    for (int n=0;n<NN;n++){
        float p = sigm_(delta[d*NN+n]);
        q[n]  = 1.f - p*sigm_(alpha[d*NN+n]);
        pb[n] = p*beta_e[d*NN+n];
        g[n]  = gamma_e[d*NN+n]*0.25f;
    }
    const float* si = sInit + (size_t)t*NN;
    #pragma unroll
    for (int n=0;n<NN;n+=4){
        float4 v = *(const float4*)(si+n);
        s[n]=v.x; s[n+1]=v.y; s[n+2]=v.z; s[n+3]=v.w;
    }
    float om = omega[d];
    const h16* xp = xn + (size_t)c*EMA_C*BD + gid;
    h16* op = mh + (size_t)c*EMA_C*BD + gid;
    for (int l=0; l<EMA_C; l++){
        float xc = __half2float(xp[(size_t)l*BD]);
        float a0=0.f,a1=0.f,a2=0.f,a3=0.f;
        #pragma unroll
        for (int n=0;n<NN;n+=4){
            s[n]   = fmaf(q[n],   s[n],   pb[n]*xc);
            s[n+1] = fmaf(q[n+1], s[n+1], pb[n+1]*xc);
            s[n+2] = fmaf(q[n+2], s[n+2], pb[n+2]*xc);
            s[n+3] = fmaf(q[n+3], s[n+3], pb[n+3]*xc);
            a0 = fmaf(g[n],   s[n],   a0);
            a1 = fmaf(g[n+1], s[n+1], a1);
            a2 = fmaf(g[n+2], s[n+2], a2);
            a3 = fmaf(g[n+3], s[n+3], a3);
        }
        float y = silu_((a0+a1)+(a2+a3) + om*xc);
        op[(size_t)l*BD] = __float2half(y);
    }
}

// ---------------- transposes ----------------
__global__ __launch_bounds__(256) void tr_w(const float* __restrict__ in,
                                            h16* __restrict__ oh, int R, int C)
{
    __shared__ float t[32][33];
    int c0 = blockIdx.x*32, r0 = blockIdx.y*32;
    int tx = threadIdx.x, ty = threadIdx.y;
    #pragma unroll
    for (int k=0;k<4;k++)
        t[ty+8*k][tx] = in[(size_t)(r0+ty+8*k)*C + c0+tx];
    __syncthreads();
    #pragma unroll
    for (int k=0;k<4;k++)
        oh[(size_t)(c0+ty+8*k)*R + r0+tx] = __float2half(t[tx][ty+8*k]);
}

__global__ __launch_bounds__(256) void tr_v(const h16* __restrict__ v,
                                            h16* __restrict__ oh)
{
    __shared__ h16 t[32][33];
    int h0 = blockIdx.x*32, l0 = blockIdx.y*32, b = blockIdx.z;
    int tx = threadIdx.x, ty = threadIdx.y;
    #pragma unroll
    for (int k=0;k<4;k++)
        t[ty+8*k][tx] = v[((size_t)(l0+ty+8*k)*8 + b)*HH + h0+tx];
    __syncthreads();
    #pragma unroll
    for (int k=0;k<4;k++)
        oh[(size_t)b*HH*LSEQ + (size_t)(h0+ty+8*k)*LSEQ + l0+tx] = t[tx][ty+8*k];
}

// ---------------- GEMM: cp.async + ldmatrix + fp16 HMMA, 128x128x32, 5 stages ----------------
struct EpiP {
    float* f0;
    h16* h0; h16* h1; h16* h2; h16* h3; h16* h4;
    const h16* auxh0; const h16* auxh1;
    const float* bias; const float* aux0; const float* aux1; const float* aux2;
    long strideC; int ldc;
};

#define STG 16384
#define NSTAGE 5

template<int EPI, int KDIM>
__global__ __launch_bounds__(256,2) void gemm_mma(
    const h16* __restrict__ Ahg, const h16* __restrict__ Bhg,
    int lda, int ldb, long sA, long sB, EpiP P)
{
    extern __shared__ char smch[];
    const uint32_t smb = sm_u32(smch);
    const int tid = threadIdx.x;
    const int w = tid>>5, lane = tid&31;
    const int m0 = blockIdx.y*128, n0 = blockIdx.x*128, bz = blockIdx.z;
    Ahg += (size_t)bz*sA;
    Bhg += (size_t)bz*sB;
    const int mw = (w&1)*64, nw = (w>>1)*32;

    const int r  = tid>>1;
    const int g0 = (tid&1)*2;
    const int sw = (r>>1)&3;
    const uint32_t d0 = (uint32_t)(r*64 + ((g0     ^ sw)<<4));
    const uint32_t d1 = (uint32_t)(r*64 + (((g0+1) ^ sw)<<4));
    const h16* sAh = Ahg + (size_t)(m0+r)*lda + g0*8;
    const h16* sBh = Bhg + (size_t)(n0+r)*ldb + g0*8;

    auto issue = [&](int kt){
        uint32_t sb = smb + (uint32_t)(kt%NSTAGE)*STG;
        const h16* a0 = sAh + (size_t)kt*32;
        const h16* b0 = sBh + (size_t)kt*32;
        CPA(sb+d0,       a0); CPA(sb+d1,       a0+8);
        CPA(sb+8192+d0,  b0); CPA(sb+8192+d1,  b0+8);
        asm volatile("cp.async.commit_group;");
    };

    const int ra   = lane&15;
    const int la16 = lane>>4;
    const int swA  = ((mw + ra)>>1)&3;
    const int rb   = (lane&7) + ((lane>>4)&1)*8;
    const int lb16 = (lane>>3)&1;
    const int swB  = ((nw + rb)>>1)&3;

    uint32_t aBase[4], bBase[2];
    #pragma unroll
    for (int a=0;a<4;a++) aBase[a] = (uint32_t)((mw+ra+a*16)*64);
    #pragma unroll
    for (int p=0;p<2;p++) bBase[p] = 8192u + (uint32_t)((nw+rb+p*16)*64);
    uint32_t koffA[2], koffB[2];
    #pragma unroll
    for (int ks=0; ks<2; ks++){
        koffA[ks] = (uint32_t)(((ks*2+la16)^swA)<<4);
        koffB[ks] = (uint32_t)(((ks*2+lb16)^swB)<<4);
    }

    float acc[4][4][4];
    #pragma unroll
    for (int a=0;a<4;a++)
        #pragma unroll
        for (int n=0;n<4;n++)
            #pragma unroll
            for (int i=0;i<4;i++) acc[a][n][i]=0.f;

    constexpr int nk = KDIM/32;
    issue(0); issue(1); issue(2);
    if (3 < nk) issue(3);

    #pragma unroll 4
    for (int kt=0; kt<nk; kt++){
        if (kt+3 < nk) asm volatile("cp.async.wait_group 3;");
        else           asm volatile("cp.async.wait_group 0;");
        __syncthreads();
        if (kt+4 < nk) issue(kt+4);

        const uint32_t sb = smb + (uint32_t)(kt%NSTAGE)*STG;
        #pragma unroll
        for (int ks=0; ks<2; ks++){
            uint32_t bh[2][4];
            #pragma unroll
            for (int p=0;p<2;p++)
                ldm4(bh[p], sb + bBase[p] + koffB[ks]);
            #pragma unroll
            for (int a=0;a<4;a++){
                uint32_t ah[4];
                ldm4(ah, sb + aBase[a] + koffA[ks]);
                #pragma unroll
                for (int n=0;n<4;n++){
                    const int p=n>>1, q=(n&1)*2;
                    mma16816(acc[a][n], ah, bh[p][q], bh[p][q+1]);
                }
            }
        }
    }

    // ---------------- epilogue ----------------
    #pragma unroll
    for (int a=0;a<4;a++){
        #pragma unroll
        for (int n=0;n<4;n++){
            const int gj = n0 + nw + n*8 + (lane&3)*2;
            #pragma unroll
            for (int half=0; half<2; half++){
                const int gi = m0 + mw + a*16 + (lane>>2) + half*8;
                float v0 = acc[a][n][half*2+0];
                float v1 = acc[a][n][half*2+1];
                if (EPI==0){
                    st2(P.h0, (size_t)gi*P.ldc + gj,
                        silu_(v0 + P.bias[gj]), silu_(v1 + P.bias[gj+1]));
                } else if (EPI==1){
                    v0 += P.bias[gj]; v1 += P.bias[gj+1];
                    if (n0 < DD){
                        st2(P.h3, (size_t)gi*DD + gj, sigm_(v0), sigm_(v1));
                    } else if (n0 < DD+ZZ){
                        int zi = gj - DD;
                        int l = gi>>3, b = gi&7;
                        size_t qi = ((size_t)b*LSEQ + l)*ZZ + zi;
                        float z0 = silu_(v0), z1 = silu_(v1);
                        float q0 = z0*P.aux0[zi]   + P.aux1[zi];
                        float q1 = z1*P.aux0[zi+1] + P.aux1[zi+1];
                        float k0 = z0*P.aux0[ZZ+zi]   + P.aux1[ZZ+zi];
                        float k1 = z1*P.aux0[ZZ+zi+1] + P.aux1[ZZ+zi+1];
                        st2(P.h0, qi, q0, q1);
                        st2(P.h2, qi, k0, k1);
                    } else if (n0 < DD+ZZ+HH){
                        st2(P.h1, (size_t)gi*HH + (gj-(DD+ZZ)),
                            silu_(v0), silu_(v1));
                    } else {
                        st2(P.h4, (size_t)gi*DD + (gj-(DD+ZZ+HH)), v0, v1);
                    }
                } else if (EPI==2){
                    const float invL = 1.0f/LSEQ;
                    const float* rel = P.aux0 + (LSEQ-1) - gi + gj;
                    float o0 = laplace_(v0*invL + rel[0]);
                    float o1 = laplace_(v1*invL + rel[1]);
                    st2(P.h0, (size_t)bz*P.strideC + (size_t)gi*P.ldc + gj, o0, o1);
                } else if (EPI==3){
                    size_t idx = ((size_t)gi*8 + bz)*HH + gj;
                    __half2 rr = *(const __half2*)&P.auxh0[idx];
                    st2(P.h0, idx, v0*__half2float(rr.x), v1*__half2float(rr.y));
                } else {
                    size_t idx = (size_t)gi*DD + gj;
                    float2 hb  = *(const float2*)&P.bias[gj];
                    __half2 hx2 = *(const __half2*)&P.auxh0[idx];
                    __half2 u2  = *(const __half2*)&P.auxh1[idx];
                    float2 x2  = *(const float2*)&P.aux2[idx];
                    float t0 = silu_(__half2float(hx2.x) + v0 + hb.x);
                    float t1 = silu_(__half2float(hx2.y) + v1 + hb.y);
                    float u0 = __half2float(u2.x), u1 = __half2float(u2.y);
                    float2 o = { x2.x + u0*(t0-x2.x), x2.y + u1*(t1-x2.y) };
                    *(float2*)&P.f0[idx] = o;
                }
            }
        }
    }
}

// ---------------- host ----------------
static const int GEMM_SMEM = NSTAGE*STG;   // 81920

extern "C" void kernel_launch(void* const* d_in, const int* in_sizes, int n_in,
                              void* d_out, int out_size)
{
    const float* x      = (const float*)d_in[0];
    const float* delta  = (const float*)d_in[1];
    const float* alpha  = (const float*)d_in[2];
    const float* beta_e = (const float*)d_in[3];
    const float* gamma_e= (const float*)d_in[4];
    const float* omega  = (const float*)d_in[5];
    const float* v_w    = (const float*)d_in[6];
    const float* v_b    = (const float*)d_in[7];
    const float* mx_w   = (const float*)d_in[8];
    const float* mx_b   = (const float*)d_in[9];
    const float* h_w    = (const float*)d_in[10];
    const float* h_b    = (const float*)d_in[11];
    const float* qk_g   = (const float*)d_in[12];
    const float* qk_b   = (const float*)d_in[13];
    const float* rel    = (const float*)d_in[14];
    const float* ln_w   = (const float*)d_in[15];
    const float* ln_b   = (const float*)d_in[16];
    float* out = (float*)d_out;

    h16 *uh,*hxh,*vh,*rh,*xnh,*mxh,*qh,*ath,*hrh,*vw,*mxw,*hw,*kk,*vT;
    float *sEnd,*sInit;
    cudaGetSymbolAddress((void**)&uh,  g_uh);
    cudaGetSymbolAddress((void**)&hxh, g_hxh);
    cudaGetSymbolAddress((void**)&vh,  g_vh);
    cudaGetSymbolAddress((void**)&rh,  g_rh);
    cudaGetSymbolAddress((void**)&xnh, g_xnh);
    cudaGetSymbolAddress((void**)&mxh, g_mxh);
    cudaGetSymbolAddress((void**)&qh,  g_qh);
    cudaGetSymbolAddress((void**)&ath, g_ath);
    cudaGetSymbolAddress((void**)&hrh, g_hrh);
    cudaGetSymbolAddress((void**)&vw,  g_vw);
    cudaGetSymbolAddress((void**)&mxw, g_mxw);
    cudaGetSymbolAddress((void**)&hw,  g_hw);
    cudaGetSymbolAddress((void**)&kk,  g_k);
    cudaGetSymbolAddress((void**)&vT,  g_vT);
    cudaGetSymbolAddress((void**)&sEnd,  g_sEnd);
    cudaGetSymbolAddress((void**)&sInit, g_sInit);

    cudaFuncSetAttribute(gemm_mma<0,DD>, cudaFuncAttributeMaxDynamicSharedMemorySize, GEMM_SMEM);
    cudaFuncSetAttribute(gemm_mma<1,DD>, cudaFuncAttributeMaxDynamicSharedMemorySize, GEMM_SMEM);
    cudaFuncSetAttribute(gemm_mma<2,ZZ>, cudaFuncAttributeMaxDynamicSharedMemorySize, GEMM_SMEM);
    cudaFuncSetAttribute(gemm_mma<3,LSEQ>, cudaFuncAttributeMaxDynamicSharedMemorySize, GEMM_SMEM);
    cudaFuncSetAttribute(gemm_mma<4,HH>, cudaFuncAttributeMaxDynamicSharedMemorySize, GEMM_SMEM);

    dim3 tb(32,8);

    // weight transposes -> single fp16 [N,K]
    tr_w<<<dim3(HH/32,  DD/32), tb>>>(v_w,  vw,  DD, HH);
    tr_w<<<dim3(NBASE/32, DD/32), tb>>>(mx_w, mxw, DD, NBASE);
    tr_w<<<dim3(DD/32,  HH/32), tb>>>(h_w,  hw,  HH, DD);

    // 1) layernorm -> fp16
    ln_kernel<<<MROWS, 256>>>(x, ln_w, ln_b, xnh);

    // 2) EMA parallel scan (3 passes, 16x chunk parallelism)
    ema1_kernel<<<(EMA_NC*BD)/256, 256>>>(xnh, delta, alpha, beta_e, sEnd);
    ema2_kernel<<<BD/256, 256>>>(delta, alpha, sEnd, sInit);
    ema3_kernel<<<(EMA_NC*BD)/256, 256>>>(xnh, delta, alpha, beta_e, gamma_e, omega, sInit, mxh);

    // 3) v = silu(xn @ v_w + v_b) -> fp16 (L,B,H)
    {
        EpiP P = {}; P.h0 = vh; P.bias = v_b; P.ldc = HH;
        gemm_mma<0,DD><<<dim3(HH/128, MROWS/128, 1), 256, GEMM_SMEM>>>(
            xnh, vw, DD, DD, 0, 0, P);
    }
    tr_v<<<dim3(HH/32, LSEQ/32, BB), tb>>>(vh, vT);

    // 4) base GEMM + split epilogue
    {
        EpiP P = {};
        P.h0=qh; P.h1=rh; P.h2=kk; P.h3=uh; P.h4=hxh;
        P.bias=mx_b; P.aux0=qk_g; P.aux1=qk_b;
        gemm_mma<1,DD><<<dim3(NBASE/128, MROWS/128, 1), 256, GEMM_SMEM>>>(
            mxh, mxw, DD, DD, 0, 0, P);
    }
    // 5) attn = laplace(q@k^T/L + bias) -> fp16
    {
        EpiP P = {}; P.h0 = ath; P.aux0 = rel; P.ldc = LSEQ;
        P.strideC = (long)LSEQ*LSEQ;
        gemm_mma<2,ZZ><<<dim3(LSEQ/128, LSEQ/128, BB), 256, GEMM_SMEM>>>(
            qh, kk, ZZ, ZZ, (long)LSEQ*ZZ, (long)LSEQ*ZZ, P);
    }
    // 6) hr = (attn @ vb) * r -> fp16 (L,B,H)
    {
        EpiP P = {}; P.h0 = hrh; P.auxh0 = rh;
        gemm_mma<3,LSEQ><<<dim3(HH/128, LSEQ/128, BB), 256, GEMM_SMEM>>>(
            ath, vT, LSEQ, LSEQ, (long)LSEQ*LSEQ, (long)HH*LSEQ, P);
    }
    // 7) out = x + u*(silu(hx + hr@h_w + h_b) - x)
    {
        EpiP P = {}; P.f0 = out; P.bias = h_b; P.auxh0 = hxh; P.auxh1 = uh; P.aux2 = x;
        gemm_mma<4,HH><<<dim3(DD/128, MROWS/128, 1), 256, GEMM_SMEM>>>(
            hrh, hw, HH, HH, 0, 0, P);
    }
}

// round 16
// speedup vs baseline: 1.0323x; 1.0323x over previous
#include <cuda_runtime.h>
#include <cuda_fp16.h>
#include <math.h>
#include <stdint.h>

// ---------------- problem constants ----------------
#define LSEQ 2048
#define BB   8
#define DD   1024
#define ZZ   128
#define HH   2048
#define NN   16
#define MROWS (LSEQ*BB)           // 16384
#define NBASE (ZZ+HH+2*DD)        // 4224
#define EMA_C  128
#define EMA_NC (LSEQ/EMA_C)       // 16
#define BD (BB*DD)                // 8192

typedef __half h16;

// ---------------- scratch ----------------
__device__ h16 g_uh [(size_t)MROWS*DD];
__device__ h16 g_hxh[(size_t)MROWS*DD];
__device__ h16 g_vh [(size_t)MROWS*HH];
__device__ h16 g_rh [(size_t)MROWS*HH];
__device__ h16 g_xnh[(size_t)MROWS*DD];
__device__ h16 g_mxh[(size_t)MROWS*DD];
__device__ h16 g_qh [(size_t)BB*LSEQ*ZZ];
__device__ h16 g_ath[(size_t)BB*LSEQ*LSEQ];
__device__ h16 g_hrh[(size_t)MROWS*HH];
__device__ h16 g_vw [(size_t)HH*DD];
__device__ h16 g_mxw[(size_t)NBASE*DD];
__device__ h16 g_hw [(size_t)DD*HH];
__device__ h16 g_k  [(size_t)BB*LSEQ*ZZ];
__device__ h16 g_vT [(size_t)BB*HH*LSEQ];
__device__ float g_sEnd [(size_t)EMA_NC*BD*NN];   // 8 MB
__device__ float g_sInit[(size_t)EMA_NC*BD*NN];   // 8 MB

// ---------------- math helpers ----------------
__device__ __forceinline__ float sigm_(float x){ return 1.f/(1.f+expf(-x)); }
__device__ __forceinline__ float silu_(float x){ return x/(1.f+expf(-x)); }
__device__ __forceinline__ float laplace_(float x){
    const float inv = (float)(1.0/(0.282095*1.4142135623730951));
    return 0.5f*(1.f + erff((x - 0.707107f) * inv));
}
__device__ __forceinline__ uint32_t sm_u32(const void* p){
    uint32_t a;
    asm("{ .reg .u64 t; cvta.to.shared.u64 t, %1; cvt.u32.u64 %0, t; }" : "=r"(a) : "l"(p));
    return a;
}
__device__ __forceinline__ void ldm4(uint32_t* r, uint32_t addr){
    asm volatile("ldmatrix.sync.aligned.m8n8.x4.shared.b16 {%0,%1,%2,%3}, [%4];"
        : "=r"(r[0]),"=r"(r[1]),"=r"(r[2]),"=r"(r[3]) : "r"(addr));
}
__device__ __forceinline__ void mma16816(float* c, const uint32_t* a, uint32_t b0, uint32_t b1){
    asm volatile("mma.sync.aligned.m16n8k16.row.col.f32.f16.f16.f32 "
        "{%0,%1,%2,%3}, {%4,%5,%6,%7}, {%8,%9}, {%0,%1,%2,%3};"
        : "+f"(c[0]),"+f"(c[1]),"+f"(c[2]),"+f"(c[3])
        : "r"(a[0]),"r"(a[1]),"r"(a[2]),"r"(a[3]),"r"(b0),"r"(b1));
}
#define CPA(dst, src) asm volatile("cp.async.cg.shared.global [%0], [%1], 16;" :: "r"(dst), "l"(src))

__device__ __forceinline__ void st2(h16* H, size_t idx, float v0, float v1){
    __half2 t; t.x=__float2half(v0); t.y=__float2half(v1);
    *(__half2*)(H+idx) = t;
}
__device__ __forceinline__ uint2 pack4(float4 v){
    uint2 h;
    h16 h0=__float2half(v.x), h1=__float2half(v.y), h2=__float2half(v.z), h3=__float2half(v.w);
    h.x = (uint32_t)__half_as_ushort(h0) | ((uint32_t)__half_as_ushort(h1)<<16);
    h.y = (uint32_t)__half_as_ushort(h2) | ((uint32_t)__half_as_ushort(h3)<<16);
    return h;
}

// ---------------- LayerNorm: fp16 out only ----------------
__global__ __launch_bounds__(256) void ln_kernel(
    const float* __restrict__ x, const float* __restrict__ w,
    const float* __restrict__ b, h16* __restrict__ oh)
{
    long row = blockIdx.x;
    int tid = threadIdx.x;
    float4 v = ((const float4*)(x + row*DD))[tid];
    float s  = v.x+v.y+v.z+v.w;
    float ss = fmaf(v.x,v.x, fmaf(v.y,v.y, fmaf(v.z,v.z, v.w*v.w)));
    #pragma unroll
    for (int o=16;o>0;o>>=1){
        s  += __shfl_xor_sync(0xffffffffu, s, o);
        ss += __shfl_xor_sync(0xffffffffu, ss, o);
    }
    __shared__ float sh0[8], sh1[8];
    int wid = tid>>5, lane = tid&31;
    if (lane==0){ sh0[wid]=s; sh1[wid]=ss; }
    __syncthreads();
    float S=0.f, SS=0.f;
    #pragma unroll
    for (int i=0;i<8;i++){ S += sh0[i]; SS += sh1[i]; }
    float mu  = S*(1.f/DD);
    float var = SS*(1.f/DD) - mu*mu;
    float inv = rsqrtf(var + 1e-5f);
    float4 wv = ((const float4*)w)[tid];
    float4 bv = ((const float4*)b)[tid];
    float4 o;
    o.x = (v.x-mu)*inv*wv.x + bv.x;
    o.y = (v.y-mu)*inv*wv.y + bv.y;
    o.z = (v.z-mu)*inv*wv.z + bv.z;
    o.w = (v.w-mu)*inv*wv.w + bv.w;
    *(uint2*)(oh + row*DD + tid*4) = pack4(o);
}

// ---------------- EMA parallel scan ----------------
__global__ __launch_bounds__(256) void ema1_kernel(
    const h16* __restrict__ xn,
    const float* __restrict__ delta, const float* __restrict__ alpha,
    const float* __restrict__ beta_e, float* __restrict__ sEnd)
{
    int t = blockIdx.x*256 + threadIdx.x;
    int gid = t & (BD-1);
    int c   = t >> 13;
    int d   = gid & (DD-1);
    float q[NN], pb[NN], s[NN];
    #pragma unroll
    for (int n=0;n<NN;n++){
        float p = sigm_(delta[d*NN+n]);
        q[n]  = 1.f - p*sigm_(alpha[d*NN+n]);
        pb[n] = p*beta_e[d*NN+n];
        s[n]  = 0.f;
    }
    const h16* xp = xn + (size_t)c*EMA_C*BD + gid;
    for (int l=0; l<EMA_C; l++){
        float xc = __half2float(xp[(size_t)l*BD]);
        #pragma unroll
        for (int n=0;n<NN;n++)
            s[n] = fmaf(q[n], s[n], pb[n]*xc);
    }
    float* o = sEnd + (size_t)t*NN;
    #pragma unroll
    for (int n=0;n<NN;n+=4)
        *(float4*)(o+n) = make_float4(s[n],s[n+1],s[n+2],s[n+3]);
}

__global__ __launch_bounds__(256) void ema2_kernel(
    const float* __restrict__ delta, const float* __restrict__ alpha,
    const float* __restrict__ sEnd, float* __restrict__ sInit)
{
    int gid = blockIdx.x*256 + threadIdx.x;   // 0..8191
    int d   = gid & (DD-1);
    float qc[NN], S[NN];
    #pragma unroll
    for (int n=0;n<NN;n++){
        float p = sigm_(delta[d*NN+n]);
        float q = 1.f - p*sigm_(alpha[d*NN+n]);
        float tq = q;
        #pragma unroll
        for (int i=0;i<7;i++) tq = tq*tq;     // q^128
        qc[n] = tq;
        S[n]  = 0.f;
    }
    for (int c=0; c<EMA_NC; c++){
        size_t idx = ((size_t)c*BD + gid)*NN;
        float* oi = sInit + idx;
        const float* ei = sEnd + idx;
        #pragma unroll
        for (int n=0;n<NN;n+=4){
            *(float4*)(oi+n) = make_float4(S[n],S[n+1],S[n+2],S[n+3]);
            float4 e = *(const float4*)(ei+n);
            S[n]   = fmaf(qc[n],   S[n],   e.x);
            S[n+1] = fmaf(qc[n+1], S[n+1], e.y);
            S[n+2] = fmaf(qc[n+2], S[n+2], e.z);
            S[n+3] = fmaf(qc[n+3], S[n+3], e.w);
        }
    }
}

__global__ __launch_bounds__(256) void ema3_kernel(
    const h16* __restrict__ xn,
    const float* __restrict__ delta, const float* __restrict__ alpha,
    const float* __restrict__ beta_e, const float* __restrict__ gamma_e,
    const float* __restrict__ omega, const float* __restrict__ sInit,
    h16* __restrict__ mh)
{
    int t = blockIdx.x*256 + threadIdx.x;
    int gid = t & (BD-1);
    int c   = t >> 13;
    int d   = gid & (DD-1);
    float q[NN], pb[NN], g[NN], s[NN];
    #pragma unroll
    for (int n=0;n<NN;n++){
        float p = sigm_(delta[d*NN+n]);
        q[n]  = 1.f - p*sigm_(alpha[d*NN+n]);
        pb[n] = p*beta_e[d*NN+n];
        g[n]  = gamma_e[d*NN+n]*0.25f;
    }
    const float* si = sInit + (size_t)t*NN;
    #pragma unroll
    for (int n=0;n<NN;n+=4){
        float4 v = *(const float4*)(si+n);
        s[n]=v.x; s[n+1]=v.y; s[n+2]=v.z; s[n+3]=v.w;
    }
    float om = omega[d];
    const h16* xp = xn + (size_t)c*EMA_C*BD + gid;
    h16* op = mh + (size_t)c*EMA_C*BD + gid;
    for (int l=0; l<EMA_C; l++){
        float xc = __half2float(xp[(size_t)l*BD]);
        float a0=0.f,a1=0.f,a2=0.f,a3=0.f;
        #pragma unroll
        for (int n=0;n<NN;n+=4){
            s[n]   = fmaf(q[n],   s[n],   pb[n]*xc);
            s[n+1] = fmaf(q[n+1], s[n+1], pb[n+1]*xc);
            s[n+2] = fmaf(q[n+2], s[n+2], pb[n+2]*xc);
            s[n+3] = fmaf(q[n+3], s[n+3], pb[n+3]*xc);
            a0 = fmaf(g[n],   s[n],   a0);
            a1 = fmaf(g[n+1], s[n+1], a1);
            a2 = fmaf(g[n+2], s[n+2], a2);
            a3 = fmaf(g[n+3], s[n+3], a3);
        }
        float y = silu_((a0+a1)+(a2+a3) + om*xc);
        op[(size_t)l*BD] = __float2half(y);
    }
}

// ---------------- transposes ----------------
__global__ __launch_bounds__(256) void tr_w(const float* __restrict__ in,
                                            h16* __restrict__ oh, int R, int C)
{
    __shared__ float t[32][33];
    int c0 = blockIdx.x*32, r0 = blockIdx.y*32;
    int tx = threadIdx.x, ty = threadIdx.y;
    #pragma unroll
    for (int k=0;k<4;k++)
        t[ty+8*k][tx] = in[(size_t)(r0+ty+8*k)*C + c0+tx];
    __syncthreads();
    #pragma unroll
    for (int k=0;k<4;k++)
        oh[(size_t)(c0+ty+8*k)*R + r0+tx] = __float2half(t[tx][ty+8*k]);
}

__global__ __launch_bounds__(256) void tr_v(const h16* __restrict__ v,
                                            h16* __restrict__ oh)
{
    __shared__ h16 t[32][33];
    int h0 = blockIdx.x*32, l0 = blockIdx.y*32, b = blockIdx.z;
    int tx = threadIdx.x, ty = threadIdx.y;
    #pragma unroll
    for (int k=0;k<4;k++)
        t[ty+8*k][tx] = v[((size_t)(l0+ty+8*k)*8 + b)*HH + h0+tx];
    __syncthreads();
    #pragma unroll
    for (int k=0;k<4;k++)
        oh[(size_t)b*HH*LSEQ + (size_t)(h0+ty+8*k)*LSEQ + l0+tx] = t[tx][ty+8*k];
}

// ---------------- GEMM: cp.async + ldmatrix + fp16 HMMA, 128x128x32, 4 stages ----------------
struct EpiP {
    float* f0;
    h16* h0; h16* h1; h16* h2; h16* h3; h16* h4;
    const h16* auxh0; const h16* auxh1;
    const float* bias; const float* aux0; const float* aux1; const float* aux2;
    long strideC; int ldc;
};

#define STG 16384

template<int EPI, int KDIM>
__global__ __launch_bounds__(256,2) void gemm_mma(
    const h16* __restrict__ Ahg, const h16* __restrict__ Bhg,
    int lda, int ldb, long sA, long sB, EpiP P)
{
    extern __shared__ char smch[];
    const uint32_t smb = sm_u32(smch);
    const int tid = threadIdx.x;
    const int w = tid>>5, lane = tid&31;
    const int m0 = blockIdx.y*128, n0 = blockIdx.x*128, bz = blockIdx.z;
    Ahg += (size_t)bz*sA;
    Bhg += (size_t)bz*sB;
    const int mw = (w&1)*64, nw = (w>>1)*32;

    const int r  = tid>>1;
    const int g0 = (tid&1)*2;
    const int sw = (r>>1)&3;
    const uint32_t d0 = (uint32_t)(r*64 + ((g0     ^ sw)<<4));
    const uint32_t d1 = (uint32_t)(r*64 + (((g0+1) ^ sw)<<4));
    const h16* sAh = Ahg + (size_t)(m0+r)*lda + g0*8;
    const h16* sBh = Bhg + (size_t)(n0+r)*ldb + g0*8;

    auto issue = [&](int kt){
        uint32_t sb = smb + (uint32_t)(kt&3)*STG;
        const h16* a0 = sAh + (size_t)kt*32;
        const h16* b0 = sBh + (size_t)kt*32;
        CPA(sb+d0,       a0); CPA(sb+d1,       a0+8);
        CPA(sb+8192+d0,  b0); CPA(sb+8192+d1,  b0+8);
        asm volatile("cp.async.commit_group;");
    };

    const int ra   = lane&15;
    const int la16 = lane>>4;
    const int swA  = ((mw + ra)>>1)&3;
    const int rb   = (lane&7) + ((lane>>4)&1)*8;
    const int lb16 = (lane>>3)&1;
    const int swB  = ((nw + rb)>>1)&3;

    uint32_t aBase[4], bBase[2];
    #pragma unroll
    for (int a=0;a<4;a++) aBase[a] = (uint32_t)((mw+ra+a*16)*64);
    #pragma unroll
    for (int p=0;p<2;p++) bBase[p] = 8192u + (uint32_t)((nw+rb+p*16)*64);
    uint32_t koffA[2], koffB[2];
    #pragma unroll
    for (int ks=0; ks<2; ks++){
        koffA[ks] = (uint32_t)(((ks*2+la16)^swA)<<4);
        koffB[ks] = (uint32_t)(((ks*2+lb16)^swB)<<4);
    }

    float acc[4][4][4];
    #pragma unroll
    for (int a=0;a<4;a++)
        #pragma unroll
        for (int n=0;n<4;n++)
            #pragma unroll
            for (int i=0;i<4;i++) acc[a][n][i]=0.f;

    constexpr int nk = KDIM/32;
    issue(0); issue(1); issue(2);

    #pragma unroll 4
    for (int kt=0; kt<nk; kt++){
        if (kt+2 < nk) asm volatile("cp.async.wait_group 2;");
        else           asm volatile("cp.async.wait_group 0;");
        __syncthreads();
        if (kt+3 < nk) issue(kt+3);

        const uint32_t sb = smb + (uint32_t)(kt&3)*STG;
        #pragma unroll
        for (int ks=0; ks<2; ks++){
            uint32_t bh[2][4];
            #pragma unroll
            for (int p=0;p<2;p++)
                ldm4(bh[p], sb + bBase[p] + koffB[ks]);
            #pragma unroll
            for (int a=0;a<4;a++){
                uint32_t ah[4];
                ldm4(ah, sb + aBase[a] + koffA[ks]);
                #pragma unroll
                for (int n=0;n<4;n++){
                    const int p=n>>1, q=(n&1)*2;
                    mma16816(acc[a][n], ah, bh[p][q], bh[p][q+1]);
                }
            }
        }
    }

    // ---------------- epilogue ----------------
    #pragma unroll
    for (int a=0;a<4;a++){
        #pragma unroll
        for (int n=0;n<4;n++){
            const int gj = n0 + nw + n*8 + (lane&3)*2;
            #pragma unroll
            for (int half=0; half<2; half++){
                const int gi = m0 + mw + a*16 + (lane>>2) + half*8;
                float v0 = acc[a][n][half*2+0];
                float v1 = acc[a][n][half*2+1];
                if (EPI==0){
                    st2(P.h0, (size_t)gi*P.ldc + gj,
                        silu_(v0 + P.bias[gj]), silu_(v1 + P.bias[gj+1]));
                } else if (EPI==1){
                    v0 += P.bias[gj]; v1 += P.bias[gj+1];
                    if (n0 < DD){
                        st2(P.h3, (size_t)gi*DD + gj, sigm_(v0), sigm_(v1));
                    } else if (n0 < DD+ZZ){
                        int zi = gj - DD;
                        int l = gi>>3, b = gi&7;
                        size_t qi = ((size_t)b*LSEQ + l)*ZZ + zi;
                        float z0 = silu_(v0), z1 = silu_(v1);
                        float q0 = z0*P.aux0[zi]   + P.aux1[zi];
                        float q1 = z1*P.aux0[zi+1] + P.aux1[zi+1];
                        float k0 = z0*P.aux0[ZZ+zi]   + P.aux1[ZZ+zi];
                        float k1 = z1*P.aux0[ZZ+zi+1] + P.aux1[ZZ+zi+1];
                        st2(P.h0, qi, q0, q1);
                        st2(P.h2, qi, k0, k1);
                    } else if (n0 < DD+ZZ+HH){
                        st2(P.h1, (size_t)gi*HH + (gj-(DD+ZZ)),
                            silu_(v0), silu_(v1));
                    } else {
                        st2(P.h4, (size_t)gi*DD + (gj-(DD+ZZ+HH)), v0, v1);
                    }
                } else if (EPI==2){
                    const float invL = 1.0f/LSEQ;
                    const float* rel = P.aux0 + (LSEQ-1) - gi + gj;
                    float o0 = laplace_(v0*invL + rel[0]);
                    float o1 = laplace_(v1*invL + rel[1]);
                    st2(P.h0, (size_t)bz*P.strideC + (size_t)gi*P.ldc + gj, o0, o1);
                } else if (EPI==3){
                    size_t idx = ((size_t)gi*8 + bz)*HH + gj;
                    __half2 rr = *(const __half2*)&P.auxh0[idx];
                    st2(P.h0, idx, v0*__half2float(rr.x), v1*__half2float(rr.y));
                } else {
                    size_t idx = (size_t)gi*DD + gj;
                    float2 hb  = *(const float2*)&P.bias[gj];
                    __half2 hx2 = *(const __half2*)&P.auxh0[idx];
                    __half2 u2  = *(const __half2*)&P.auxh1[idx];
                    float2 x2  = *(const float2*)&P.aux2[idx];
                    float t0 = silu_(__half2float(hx2.x) + v0 + hb.x);
                    float t1 = silu_(__half2float(hx2.y) + v1 + hb.y);
                    float u0 = __half2float(u2.x), u1 = __half2float(u2.y);
                    float2 o = { x2.x + u0*(t0-x2.x), x2.y + u1*(t1-x2.y) };
                    *(float2*)&P.f0[idx] = o;
                }
            }
        }
    }
}

// ---------------- host ----------------
static const int GEMM_SMEM = 4*STG;   // 65536

extern "C" void kernel_launch(void* const* d_in, const int* in_sizes, int n_in,
                              void* d_out, int out_size)
{
    const float* x      = (const float*)d_in[0];
    const float* delta  = (const float*)d_in[1];
    const float* alpha  = (const float*)d_in[2];
    const float* beta_e = (const float*)d_in[3];
    const float* gamma_e= (const float*)d_in[4];
    const float* omega  = (const float*)d_in[5];
    const float* v_w    = (const float*)d_in[6];
    const float* v_b    = (const float*)d_in[7];
    const float* mx_w   = (const float*)d_in[8];
    const float* mx_b   = (const float*)d_in[9];
    const float* h_w    = (const float*)d_in[10];
    const float* h_b    = (const float*)d_in[11];
    const float* qk_g   = (const float*)d_in[12];
    const float* qk_b   = (const float*)d_in[13];
    const float* rel    = (const float*)d_in[14];
    const float* ln_w   = (const float*)d_in[15];
    const float* ln_b   = (const float*)d_in[16];
    float* out = (float*)d_out;

    h16 *uh,*hxh,*vh,*rh,*xnh,*mxh,*qh,*ath,*hrh,*vw,*mxw,*hw,*kk,*vT;
    float *sEnd,*sInit;
    cudaGetSymbolAddress((void**)&uh,  g_uh);
    cudaGetSymbolAddress((void**)&hxh, g_hxh);
    cudaGetSymbolAddress((void**)&vh,  g_vh);
    cudaGetSymbolAddress((void**)&rh,  g_rh);
    cudaGetSymbolAddress((void**)&xnh, g_xnh);
    cudaGetSymbolAddress((void**)&mxh, g_mxh);
    cudaGetSymbolAddress((void**)&qh,  g_qh);
    cudaGetSymbolAddress((void**)&ath, g_ath);
    cudaGetSymbolAddress((void**)&hrh, g_hrh);
    cudaGetSymbolAddress((void**)&vw,  g_vw);
    cudaGetSymbolAddress((void**)&mxw, g_mxw);
    cudaGetSymbolAddress((void**)&hw,  g_hw);
    cudaGetSymbolAddress((void**)&kk,  g_k);
    cudaGetSymbolAddress((void**)&vT,  g_vT);
    cudaGetSymbolAddress((void**)&sEnd,  g_sEnd);
    cudaGetSymbolAddress((void**)&sInit, g_sInit);

    cudaFuncSetAttribute(gemm_mma<0,DD>, cudaFuncAttributeMaxDynamicSharedMemorySize, GEMM_SMEM);
    cudaFuncSetAttribute(gemm_mma<1,DD>, cudaFuncAttributeMaxDynamicSharedMemorySize, GEMM_SMEM);
    cudaFuncSetAttribute(gemm_mma<2,ZZ>, cudaFuncAttributeMaxDynamicSharedMemorySize, GEMM_SMEM);
    cudaFuncSetAttribute(gemm_mma<3,LSEQ>, cudaFuncAttributeMaxDynamicSharedMemorySize, GEMM_SMEM);
    cudaFuncSetAttribute(gemm_mma<4,HH>, cudaFuncAttributeMaxDynamicSharedMemorySize, GEMM_SMEM);

    dim3 tb(32,8);

    // weight transposes -> single fp16 [N,K]
    tr_w<<<dim3(HH/32,  DD/32), tb>>>(v_w,  vw,  DD, HH);
    tr_w<<<dim3(NBASE/32, DD/32), tb>>>(mx_w, mxw, DD, NBASE);
    tr_w<<<dim3(DD/32,  HH/32), tb>>>(h_w,  hw,  HH, DD);

    // 1) layernorm -> fp16
    ln_kernel<<<MROWS, 256>>>(x, ln_w, ln_b, xnh);

    // 2) EMA parallel scan (3 passes, 16x chunk parallelism)
    ema1_kernel<<<(EMA_NC*BD)/256, 256>>>(xnh, delta, alpha, beta_e, sEnd);
    ema2_kernel<<<BD/256, 256>>>(delta, alpha, sEnd, sInit);
    ema3_kernel<<<(EMA_NC*BD)/256, 256>>>(xnh, delta, alpha, beta_e, gamma_e, omega, sInit, mxh);

    // 3) v = silu(xn @ v_w + v_b) -> fp16 (L,B,H)
    {
        EpiP P = {}; P.h0 = vh; P.bias = v_b; P.ldc = HH;
        gemm_mma<0,DD><<<dim3(HH/128, MROWS/128, 1), 256, GEMM_SMEM>>>(
            xnh, vw, DD, DD, 0, 0, P);
    }
    tr_v<<<dim3(HH/32, LSEQ/32, BB), tb>>>(vh, vT);

    // 4) base GEMM + split epilogue
    {
        EpiP P = {};
        P.h0=qh; P.h1=rh; P.h2=kk; P.h3=uh; P.h4=hxh;
        P.bias=mx_b; P.aux0=qk_g; P.aux1=qk_b;
        gemm_mma<1,DD><<<dim3(NBASE/128, MROWS/128, 1), 256, GEMM_SMEM>>>(
            mxh, mxw, DD, DD, 0, 0, P);
    }
    // 5) attn = laplace(q@k^T/L + bias) -> fp16
    {
        EpiP P = {}; P.h0 = ath; P.aux0 = rel; P.ldc = LSEQ;
        P.strideC = (long)LSEQ*LSEQ;
        gemm_mma<2,ZZ><<<dim3(LSEQ/128, LSEQ/128, BB), 256, GEMM_SMEM>>>(
            qh, kk, ZZ, ZZ, (long)LSEQ*ZZ, (long)LSEQ*ZZ, P);
    }
    // 6) hr = (attn @ vb) * r -> fp16 (L,B,H)
    {
        EpiP P = {}; P.h0 = hrh; P.auxh0 = rh;
        gemm_mma<3,LSEQ><<<dim3(HH/128, LSEQ/128, BB), 256, GEMM_SMEM>>>(
            ath, vT, LSEQ, LSEQ, (long)LSEQ*LSEQ, (long)HH*LSEQ, P);
    }
    // 7) out = x + u*(silu(hx + hr@h_w + h_b) - x)
    {
        EpiP P = {}; P.f0 = out; P.bias = h_b; P.auxh0 = hxh; P.auxh1 = uh; P.aux2 = x;
        gemm_mma<4,HH><<<dim3(DD/128, MROWS/128, 1), 256, GEMM_SMEM>>>(
            hrh, hw, HH, HH, 0, 0, P);
    }
}

// round 17
// speedup vs baseline: 1.0550x; 1.0220x over previous
#include <cuda_runtime.h>
#include <cuda_fp16.h>
#include <math.h>
#include <stdint.h>

// ---------------- problem constants ----------------
#define LSEQ 2048
#define BB   8
#define DD   1024
#define ZZ   128
#define HH   2048
#define NN   16
#define MROWS (LSEQ*BB)           // 16384
#define NBASE (ZZ+HH+2*DD)        // 4224
#define EMA_C  256
#define EMA_NC (LSEQ/EMA_C)       // 8
#define BD (BB*DD)                // 8192

typedef __half h16;

// ---------------- scratch ----------------
__device__ h16 g_uh [(size_t)MROWS*DD];
__device__ h16 g_hxh[(size_t)MROWS*DD];
__device__ h16 g_vh [(size_t)MROWS*HH];
__device__ h16 g_rh [(size_t)MROWS*HH];
__device__ h16 g_xnh[(size_t)MROWS*DD];
__device__ h16 g_mxh[(size_t)MROWS*DD];
__device__ h16 g_qh [(size_t)BB*LSEQ*ZZ];
__device__ h16 g_ath[(size_t)BB*LSEQ*LSEQ];
__device__ h16 g_hrh[(size_t)MROWS*HH];
__device__ h16 g_vw [(size_t)HH*DD];
__device__ h16 g_mxw[(size_t)NBASE*DD];
__device__ h16 g_hw [(size_t)DD*HH];
__device__ h16 g_k  [(size_t)BB*LSEQ*ZZ];
__device__ h16 g_vT [(size_t)BB*HH*LSEQ];
__device__ float g_sEnd [(size_t)EMA_NC*BD*NN];   // 4 MB
__device__ float g_sInit[(size_t)EMA_NC*BD*NN];   // 4 MB

// ---------------- math helpers ----------------
__device__ __forceinline__ float sigm_(float x){ return 1.f/(1.f+expf(-x)); }
__device__ __forceinline__ float silu_(float x){ return x/(1.f+expf(-x)); }
__device__ __forceinline__ float laplace_(float x){
    const float inv = (float)(1.0/(0.282095*1.4142135623730951));
    return 0.5f*(1.f + erff((x - 0.707107f) * inv));
}
__device__ __forceinline__ uint32_t sm_u32(const void* p){
    uint32_t a;
    asm("{ .reg .u64 t; cvta.to.shared.u64 t, %1; cvt.u32.u64 %0, t; }" : "=r"(a) : "l"(p));
    return a;
}
__device__ __forceinline__ void ldm4(uint32_t* r, uint32_t addr){
    asm volatile("ldmatrix.sync.aligned.m8n8.x4.shared.b16 {%0,%1,%2,%3}, [%4];"
        : "=r"(r[0]),"=r"(r[1]),"=r"(r[2]),"=r"(r[3]) : "r"(addr));
}
__device__ __forceinline__ void mma16816(float* c, const uint32_t* a, uint32_t b0, uint32_t b1){
    asm volatile("mma.sync.aligned.m16n8k16.row.col.f32.f16.f16.f32 "
        "{%0,%1,%2,%3}, {%4,%5,%6,%7}, {%8,%9}, {%0,%1,%2,%3};"
        : "+f"(c[0]),"+f"(c[1]),"+f"(c[2]),"+f"(c[3])
        : "r"(a[0]),"r"(a[1]),"r"(a[2]),"r"(a[3]),"r"(b0),"r"(b1));
}
#define CPA(dst, src) asm volatile("cp.async.cg.shared.global [%0], [%1], 16;" :: "r"(dst), "l"(src))

__device__ __forceinline__ void st2(h16* H, size_t idx, float v0, float v1){
    __half2 t; t.x=__float2half(v0); t.y=__float2half(v1);
    *(__half2*)(H+idx) = t;
}
__device__ __forceinline__ uint2 pack4(float4 v){
    uint2 h;
    h16 h0=__float2half(v.x), h1=__float2half(v.y), h2=__float2half(v.z), h3=__float2half(v.w);
    h.x = (uint32_t)__half_as_ushort(h0) | ((uint32_t)__half_as_ushort(h1)<<16);
    h.y = (uint32_t)__half_as_ushort(h2) | ((uint32_t)__half_as_ushort(h3)<<16);
    return h;
}

// ---------------- LayerNorm: fp16 out only ----------------
__global__ __launch_bounds__(256) void ln_kernel(
    const float* __restrict__ x, const float* __restrict__ w,
    const float* __restrict__ b, h16* __restrict__ oh)
{
    long row = blockIdx.x;
    int tid = threadIdx.x;
    float4 v = ((const float4*)(x + row*DD))[tid];
    float s  = v.x+v.y+v.z+v.w;
    float ss = fmaf(v.x,v.x, fmaf(v.y,v.y, fmaf(v.z,v.z, v.w*v.w)));
    #pragma unroll
    for (int o=16;o>0;o>>=1){
        s  += __shfl_xor_sync(0xffffffffu, s, o);
        ss += __shfl_xor_sync(0xffffffffu, ss, o);
    }
    __shared__ float sh0[8], sh1[8];
    int wid = tid>>5, lane = tid&31;
    if (lane==0){ sh0[wid]=s; sh1[wid]=ss; }
    __syncthreads();
    float S=0.f, SS=0.f;
    #pragma unroll
    for (int i=0;i<8;i++){ S += sh0[i]; SS += sh1[i]; }
    float mu  = S*(1.f/DD);
    float var = SS*(1.f/DD) - mu*mu;
    float inv = rsqrtf(var + 1e-5f);
    float4 wv = ((const float4*)w)[tid];
    float4 bv = ((const float4*)b)[tid];
    float4 o;
    o.x = (v.x-mu)*inv*wv.x + bv.x;
    o.y = (v.y-mu)*inv*wv.y + bv.y;
    o.z = (v.z-mu)*inv*wv.z + bv.z;
    o.w = (v.w-mu)*inv*wv.w + bv.w;
    *(uint2*)(oh + row*DD + tid*4) = pack4(o);
}

// ---------------- EMA parallel scan (8 chunks of 256) ----------------
__global__ __launch_bounds__(256) void ema1_kernel(
    const h16* __restrict__ xn,
    const float* __restrict__ delta, const float* __restrict__ alpha,
    const float* __restrict__ beta_e, float* __restrict__ sEnd)
{
    int t = blockIdx.x*256 + threadIdx.x;     // 0..65535
    int gid = t & (BD-1);
    int c   = t >> 13;
    int d   = gid & (DD-1);
    float q[NN], pb[NN], s[NN];
    #pragma unroll
    for (int n=0;n<NN;n++){
        float p = sigm_(delta[d*NN+n]);
        q[n]  = 1.f - p*sigm_(alpha[d*NN+n]);
        pb[n] = p*beta_e[d*NN+n];
        s[n]  = 0.f;
    }
    const h16* xp = xn + (size_t)c*EMA_C*BD + gid;
    for (int l=0; l<EMA_C; l++){
        float xc = __half2float(xp[(size_t)l*BD]);
        #pragma unroll
        for (int n=0;n<NN;n++)
            s[n] = fmaf(q[n], s[n], pb[n]*xc);
    }
    float* o = sEnd + (size_t)t*NN;
    #pragma unroll
    for (int n=0;n<NN;n+=4)
        *(float4*)(o+n) = make_float4(s[n],s[n+1],s[n+2],s[n+3]);
}

__global__ __launch_bounds__(256) void ema2_kernel(
    const float* __restrict__ delta, const float* __restrict__ alpha,
    const float* __restrict__ sEnd, float* __restrict__ sInit)
{
    int gid = blockIdx.x*256 + threadIdx.x;   // 0..8191
    int d   = gid & (DD-1);
    float qc[NN], S[NN];
    #pragma unroll
    for (int n=0;n<NN;n++){
        float p = sigm_(delta[d*NN+n]);
        float q = 1.f - p*sigm_(alpha[d*NN+n]);
        float tq = q;
        #pragma unroll
        for (int i=0;i<8;i++) tq = tq*tq;     // q^256
        qc[n] = tq;
        S[n]  = 0.f;
    }
    for (int c=0; c<EMA_NC; c++){
        size_t idx = ((size_t)c*BD + gid)*NN;
        float* oi = sInit + idx;
        const float* ei = sEnd + idx;
        #pragma unroll
        for (int n=0;n<NN;n+=4){
            *(float4*)(oi+n) = make_float4(S[n],S[n+1],S[n+2],S[n+3]);
            float4 e = *(const float4*)(ei+n);
            S[n]   = fmaf(qc[n],   S[n],   e.x);
            S[n+1] = fmaf(qc[n+1], S[n+1], e.y);
            S[n+2] = fmaf(qc[n+2], S[n+2], e.z);
            S[n+3] = fmaf(qc[n+3], S[n+3], e.w);
        }
    }
}

__global__ __launch_bounds__(256) void ema3_kernel(
    const h16* __restrict__ xn,
    const float* __restrict__ delta, const float* __restrict__ alpha,
    const float* __restrict__ beta_e, const float* __restrict__ gamma_e,
    const float* __restrict__ omega, const float* __restrict__ sInit,
    h16* __restrict__ mh)
{
    int t = blockIdx.x*256 + threadIdx.x;
    int gid = t & (BD-1);
    int c   = t >> 13;
    int d   = gid & (DD-1);
    float q[NN], pb[NN], g[NN], s[NN];
    #pragma unroll
    for (int n=0;n<NN;n++){
        float p = sigm_(delta[d*NN+n]);
        q[n]  = 1.f - p*sigm_(alpha[d*NN+n]);
        pb[n] = p*beta_e[d*NN+n];
        g[n]  = gamma_e[d*NN+n]*0.25f;
    }
    const float* si = sInit + (size_t)t*NN;
    #pragma unroll
    for (int n=0;n<NN;n+=4){
        float4 v = *(const float4*)(si+n);
        s[n]=v.x; s[n+1]=v.y; s[n+2]=v.z; s[n+3]=v.w;
    }
    float om = omega[d];
    const h16* xp = xn + (size_t)c*EMA_C*BD + gid;
    h16* op = mh + (size_t)c*EMA_C*BD + gid;
    for (int l=0; l<EMA_C; l++){
        float xc = __half2float(xp[(size_t)l*BD]);
        float a0=0.f,a1=0.f,a2=0.f,a3=0.f;
        #pragma unroll
        for (int n=0;n<NN;n+=4){
            s[n]   = fmaf(q[n],   s[n],   pb[n]*xc);
            s[n+1] = fmaf(q[n+1], s[n+1], pb[n+1]*xc);
            s[n+2] = fmaf(q[n+2], s[n+2], pb[n+2]*xc);
            s[n+3] = fmaf(q[n+3], s[n+3], pb[n+3]*xc);
            a0 = fmaf(g[n],   s[n],   a0);
            a1 = fmaf(g[n+1], s[n+1], a1);
            a2 = fmaf(g[n+2], s[n+2], a2);
            a3 = fmaf(g[n+3], s[n+3], a3);
        }
        float y = silu_((a0+a1)+(a2+a3) + om*xc);
        op[(size_t)l*BD] = __float2half(y);
    }
}

// ---------------- transposes ----------------
__global__ __launch_bounds__(256) void tr_w(const float* __restrict__ in,
                                            h16* __restrict__ oh, int R, int C)
{
    __shared__ float t[32][33];
    int c0 = blockIdx.x*32, r0 = blockIdx.y*32;
    int tx = threadIdx.x, ty = threadIdx.y;
    #pragma unroll
    for (int k=0;k<4;k++)
        t[ty+8*k][tx] = in[(size_t)(r0+ty+8*k)*C + c0+tx];
    __syncthreads();
    #pragma unroll
    for (int k=0;k<4;k++)
        oh[(size_t)(c0+ty+8*k)*R + r0+tx] = __float2half(t[tx][ty+8*k]);
}

__global__ __launch_bounds__(256) void tr_v(const h16* __restrict__ v,
                                            h16* __restrict__ oh)
{
    __shared__ h16 t[32][33];
    int h0 = blockIdx.x*32, l0 = blockIdx.y*32, b = blockIdx.z;
    int tx = threadIdx.x, ty = threadIdx.y;
    #pragma unroll
    for (int k=0;k<4;k++)
        t[ty+8*k][tx] = v[((size_t)(l0+ty+8*k)*8 + b)*HH + h0+tx];
    __syncthreads();
    #pragma unroll
    for (int k=0;k<4;k++)
        oh[(size_t)b*HH*LSEQ + (size_t)(h0+ty+8*k)*LSEQ + l0+tx] = t[tx][ty+8*k];
}

// ---------------- GEMM: cp.async + ldmatrix + fp16 HMMA, 128x128x32, 4 stages ----------------
struct EpiP {
    float* f0;
    h16* h0; h16* h1; h16* h2; h16* h3; h16* h4;
    const h16* auxh0; const h16* auxh1;
    const float* bias; const float* aux0; const float* aux1; const float* aux2;
    long strideC; int ldc;
};

#define STG 16384

template<int EPI, int KDIM>
__global__ __launch_bounds__(256,2) void gemm_mma(
    const h16* __restrict__ Ahg, const h16* __restrict__ Bhg,
    int lda, int ldb, long sA, long sB, EpiP P)
{
    extern __shared__ char smch[];
    const uint32_t smb = sm_u32(smch);
    const int tid = threadIdx.x;
    const int w = tid>>5, lane = tid&31;
    const int m0 = blockIdx.y*128, n0 = blockIdx.x*128, bz = blockIdx.z;
    Ahg += (size_t)bz*sA;
    Bhg += (size_t)bz*sB;
    const int mw = (w&1)*64, nw = (w>>1)*32;

    const int r  = tid>>1;
    const int g0 = (tid&1)*2;
    const int sw = (r>>1)&3;
    const uint32_t d0 = (uint32_t)(r*64 + ((g0     ^ sw)<<4));
    const uint32_t d1 = (uint32_t)(r*64 + (((g0+1) ^ sw)<<4));
    const h16* sAh = Ahg + (size_t)(m0+r)*lda + g0*8;
    const h16* sBh = Bhg + (size_t)(n0+r)*ldb + g0*8;

    auto issue = [&](int kt){
        uint32_t sb = smb + (uint32_t)(kt&3)*STG;
        const h16* a0 = sAh + (size_t)kt*32;
        const h16* b0 = sBh + (size_t)kt*32;
        CPA(sb+d0,       a0); CPA(sb+d1,       a0+8);
        CPA(sb+8192+d0,  b0); CPA(sb+8192+d1,  b0+8);
        asm volatile("cp.async.commit_group;");
    };

    const int ra   = lane&15;
    const int la16 = lane>>4;
    const int swA  = ((mw + ra)>>1)&3;
    const int rb   = (lane&7) + ((lane>>4)&1)*8;
    const int lb16 = (lane>>3)&1;
    const int swB  = ((nw + rb)>>1)&3;

    uint32_t aBase[4], bBase[2];
    #pragma unroll
    for (int a=0;a<4;a++) aBase[a] = (uint32_t)((mw+ra+a*16)*64);
    #pragma unroll
    for (int p=0;p<2;p++) bBase[p] = 8192u + (uint32_t)((nw+rb+p*16)*64);
    uint32_t koffA[2], koffB[2];
    #pragma unroll
    for (int ks=0; ks<2; ks++){
        koffA[ks] = (uint32_t)(((ks*2+la16)^swA)<<4);
        koffB[ks] = (uint32_t)(((ks*2+lb16)^swB)<<4);
    }

    float acc[4][4][4];
    #pragma unroll
    for (int a=0;a<4;a++)
        #pragma unroll
        for (int n=0;n<4;n++)
            #pragma unroll
            for (int i=0;i<4;i++) acc[a][n][i]=0.f;

    constexpr int nk = KDIM/32;
    issue(0); issue(1); issue(2);

    #pragma unroll 4
    for (int kt=0; kt<nk; kt++){
        if (kt+2 < nk) asm volatile("cp.async.wait_group 2;");
        else           asm volatile("cp.async.wait_group 0;");
        __syncthreads();
        if (kt+3 < nk) issue(kt+3);

        const uint32_t sb = smb + (uint32_t)(kt&3)*STG;
        #pragma unroll
        for (int ks=0; ks<2; ks++){
            uint32_t bh[2][4];
            #pragma unroll
            for (int p=0;p<2;p++)
                ldm4(bh[p], sb + bBase[p] + koffB[ks]);
            #pragma unroll
            for (int a=0;a<4;a++){
                uint32_t ah[4];
                ldm4(ah, sb + aBase[a] + koffA[ks]);
                #pragma unroll
                for (int n=0;n<4;n++){
                    const int p=n>>1, q=(n&1)*2;
                    mma16816(acc[a][n], ah, bh[p][q], bh[p][q+1]);
                }
            }
        }
    }

    // ---------------- epilogue ----------------
    #pragma unroll
    for (int a=0;a<4;a++){
        #pragma unroll
        for (int n=0;n<4;n++){
            const int gj = n0 + nw + n*8 + (lane&3)*2;
            #pragma unroll
            for (int half=0; half<2; half++){
                const int gi = m0 + mw + a*16 + (lane>>2) + half*8;
                float v0 = acc[a][n][half*2+0];
                float v1 = acc[a][n][half*2+1];
                if (EPI==0){
                    st2(P.h0, (size_t)gi*P.ldc + gj,
                        silu_(v0 + P.bias[gj]), silu_(v1 + P.bias[gj+1]));
                } else if (EPI==1){
                    v0 += P.bias[gj]; v1 += P.bias[gj+1];
                    if (n0 < DD){
                        st2(P.h3, (size_t)gi*DD + gj, sigm_(v0), sigm_(v1));
                    } else if (n0 < DD+ZZ){
                        int zi = gj - DD;
                        int l = gi>>3, b = gi&7;
                        size_t qi = ((size_t)b*LSEQ + l)*ZZ + zi;
                        float z0 = silu_(v0), z1 = silu_(v1);
                        float q0 = z0*P.aux0[zi]   + P.aux1[zi];
                        float q1 = z1*P.aux0[zi+1] + P.aux1[zi+1];
                        float k0 = z0*P.aux0[ZZ+zi]   + P.aux1[ZZ+zi];
                        float k1 = z1*P.aux0[ZZ+zi+1] + P.aux1[ZZ+zi+1];
                        st2(P.h0, qi, q0, q1);
                        st2(P.h2, qi, k0, k1);
                    } else if (n0 < DD+ZZ+HH){
                        st2(P.h1, (size_t)gi*HH + (gj-(DD+ZZ)),
                            silu_(v0), silu_(v1));
                    } else {
                        st2(P.h4, (size_t)gi*DD + (gj-(DD+ZZ+HH)), v0, v1);
                    }
                } else if (EPI==2){
                    const float invL = 1.0f/LSEQ;
                    const float* rel = P.aux0 + (LSEQ-1) - gi + gj;
                    float o0 = laplace_(v0*invL + rel[0]);
                    float o1 = laplace_(v1*invL + rel[1]);
                    st2(P.h0, (size_t)bz*P.strideC + (size_t)gi*P.ldc + gj, o0, o1);
                } else if (EPI==3){
                    size_t idx = ((size_t)gi*8 + bz)*HH + gj;
                    __half2 rr = *(const __half2*)&P.auxh0[idx];
                    st2(P.h0, idx, v0*__half2float(rr.x), v1*__half2float(rr.y));
                } else {
                    size_t idx = (size_t)gi*DD + gj;
                    float2 hb  = *(const float2*)&P.bias[gj];
                    __half2 hx2 = *(const __half2*)&P.auxh0[idx];
                    __half2 u2  = *(const __half2*)&P.auxh1[idx];
                    float2 x2  = *(const float2*)&P.aux2[idx];
                    float t0 = silu_(__half2float(hx2.x) + v0 + hb.x);
                    float t1 = silu_(__half2float(hx2.y) + v1 + hb.y);
                    float u0 = __half2float(u2.x), u1 = __half2float(u2.y);
                    float2 o = { x2.x + u0*(t0-x2.x), x2.y + u1*(t1-x2.y) };
                    *(float2*)&P.f0[idx] = o;
                }
            }
        }
    }
}

// ---------------- host ----------------
static const int GEMM_SMEM = 4*STG;   // 65536

extern "C" void kernel_launch(void* const* d_in, const int* in_sizes, int n_in,
                              void* d_out, int out_size)
{
    const float* x      = (const float*)d_in[0];
    const float* delta  = (const float*)d_in[1];
    const float* alpha  = (const float*)d_in[2];
    const float* beta_e = (const float*)d_in[3];
    const float* gamma_e= (const float*)d_in[4];
    const float* omega  = (const float*)d_in[5];
    const float* v_w    = (const float*)d_in[6];
    const float* v_b    = (const float*)d_in[7];
    const float* mx_w   = (const float*)d_in[8];
    const float* mx_b   = (const float*)d_in[9];
    const float* h_w    = (const float*)d_in[10];
    const float* h_b    = (const float*)d_in[11];
    const float* qk_g   = (const float*)d_in[12];
    const float* qk_b   = (const float*)d_in[13];
    const float* rel    = (const float*)d_in[14];
    const float* ln_w   = (const float*)d_in[15];
    const float* ln_b   = (const float*)d_in[16];
    float* out = (float*)d_out;

    h16 *uh,*hxh,*vh,*rh,*xnh,*mxh,*qh,*ath,*hrh,*vw,*mxw,*hw,*kk,*vT;
    float *sEnd,*sInit;
    cudaGetSymbolAddress((void**)&uh,  g_uh);
    cudaGetSymbolAddress((void**)&hxh, g_hxh);
    cudaGetSymbolAddress((void**)&vh,  g_vh);
    cudaGetSymbolAddress((void**)&rh,  g_rh);
    cudaGetSymbolAddress((void**)&xnh, g_xnh);
    cudaGetSymbolAddress((void**)&mxh, g_mxh);
    cudaGetSymbolAddress((void**)&qh,  g_qh);
    cudaGetSymbolAddress((void**)&ath, g_ath);
    cudaGetSymbolAddress((void**)&hrh, g_hrh);
    cudaGetSymbolAddress((void**)&vw,  g_vw);
    cudaGetSymbolAddress((void**)&mxw, g_mxw);
    cudaGetSymbolAddress((void**)&hw,  g_hw);
    cudaGetSymbolAddress((void**)&kk,  g_k);
    cudaGetSymbolAddress((void**)&vT,  g_vT);
    cudaGetSymbolAddress((void**)&sEnd,  g_sEnd);
    cudaGetSymbolAddress((void**)&sInit, g_sInit);

    cudaFuncSetAttribute(gemm_mma<0,DD>, cudaFuncAttributeMaxDynamicSharedMemorySize, GEMM_SMEM);
    cudaFuncSetAttribute(gemm_mma<1,DD>, cudaFuncAttributeMaxDynamicSharedMemorySize, GEMM_SMEM);
    cudaFuncSetAttribute(gemm_mma<2,ZZ>, cudaFuncAttributeMaxDynamicSharedMemorySize, GEMM_SMEM);
    cudaFuncSetAttribute(gemm_mma<3,LSEQ>, cudaFuncAttributeMaxDynamicSharedMemorySize, GEMM_SMEM);
    cudaFuncSetAttribute(gemm_mma<4,HH>, cudaFuncAttributeMaxDynamicSharedMemorySize, GEMM_SMEM);

    dim3 tb(32,8);

    // weight transposes -> single fp16 [N,K]
    tr_w<<<dim3(HH/32,  DD/32), tb>>>(v_w,  vw,  DD, HH);
    tr_w<<<dim3(NBASE/32, DD/32), tb>>>(mx_w, mxw, DD, NBASE);
    tr_w<<<dim3(DD/32,  HH/32), tb>>>(h_w,  hw,  HH, DD);

    // 1) layernorm -> fp16
    ln_kernel<<<MROWS, 256>>>(x, ln_w, ln_b, xnh);

    // 2) EMA parallel scan (3 passes, 8x chunk parallelism)
    ema1_kernel<<<(EMA_NC*BD)/256, 256>>>(xnh, delta, alpha, beta_e, sEnd);
    ema2_kernel<<<BD/256, 256>>>(delta, alpha, sEnd, sInit);
    ema3_kernel<<<(EMA_NC*BD)/256, 256>>>(xnh, delta, alpha, beta_e, gamma_e, omega, sInit, mxh);

    // 3) v = silu(xn @ v_w + v_b) -> fp16 (L,B,H)
    {
        EpiP P = {}; P.h0 = vh; P.bias = v_b; P.ldc = HH;
        gemm_mma<0,DD><<<dim3(HH/128, MROWS/128, 1), 256, GEMM_SMEM>>>(
            xnh, vw, DD, DD, 0, 0, P);
    }
    tr_v<<<dim3(HH/32, LSEQ/32, BB), tb>>>(vh, vT);

    // 4) base GEMM + split epilogue
    {
        EpiP P = {};
        P.h0=qh; P.h1=rh; P.h2=kk; P.h3=uh; P.h4=hxh;
        P.bias=mx_b; P.aux0=qk_g; P.aux1=qk_b;
        gemm_mma<1,DD><<<dim3(NBASE/128, MROWS/128, 1), 256, GEMM_SMEM>>>(
            mxh, mxw, DD, DD, 0, 0, P);
    }
    // 5) attn = laplace(q@k^T/L + bias) -> fp16
    {
        EpiP P = {}; P.h0 = ath; P.aux0 = rel; P.ldc = LSEQ;
        P.strideC = (long)LSEQ*LSEQ;
        gemm_mma<2,ZZ><<<dim3(LSEQ/128, LSEQ/128, BB), 256, GEMM_SMEM>>>(
            qh, kk, ZZ, ZZ, (long)LSEQ*ZZ, (long)LSEQ*ZZ, P);
    }
    // 6) hr = (attn @ vb) * r -> fp16 (L,B,H)
    {
        EpiP P = {}; P.h0 = hrh; P.auxh0 = rh;
        gemm_mma<3,LSEQ><<<dim3(HH/128, LSEQ/128, BB), 256, GEMM_SMEM>>>(
            ath, vT, LSEQ, LSEQ, (long)LSEQ*LSEQ, (long)HH*LSEQ, P);
    }
    // 7) out = x + u*(silu(hx + hr@h_w + h_b) - x)
    {
        EpiP P = {}; P.f0 = out; P.bias = h_b; P.auxh0 = hxh; P.auxh1 = uh; P.aux2 = x;
        gemm_mma<4,HH><<<dim3(DD/128, MROWS/128, 1), 256, GEMM_SMEM>>>(
            hrh, hw, HH, HH, 0, 0, P);
    }
}